// round 3
// baseline (speedup 1.0000x reference)
#include <cuda_runtime.h>

#define Bn 256
#define EPS 1e-6f

// ---- scratch (allocation-free rule: __device__ globals) ----
__device__ float g_metric[Bn * 256];       // symmetrized metric, (b,16,16)
__device__ float g_pa[Bn * 256];           // points@rW1[0:16] + rb1
__device__ float g_ar[Bn * 16 * 256];      // metric_row_i @ rW1[16:32]
__device__ float g_br[Bn * 16 * 256];      // metric_row_j @ rW1[32:48]
__device__ float g_spart[Bn * 16 * 256];   // partial relu-sums per (b,i)

__device__ __forceinline__ float tanh_fast(float x) {
    float y;
    asm("tanh.approx.f32 %0, %1;" : "=f"(y) : "f"(x));
    return y;
}

// ---------------------------------------------------------------------------
// Kernel 1: per-batch metric MLP + linear precomputes for the ricci layer-1.
// grid = 256 (batch), block = 256.
// ---------------------------------------------------------------------------
__global__ void prep_kernel(const float* __restrict__ points,
                            const float* __restrict__ mW1, const float* __restrict__ mb1,
                            const float* __restrict__ mW2, const float* __restrict__ mb2,
                            const float* __restrict__ rW1, const float* __restrict__ rb1)
{
    int b = blockIdx.x;
    int t = threadIdx.x;
    __shared__ float p_s[16];
    __shared__ float mh_s[128];
    __shared__ float raw_s[256];
    __shared__ float met_s[256];

    if (t < 16) p_s[t] = points[b * 16 + t];
    __syncthreads();

    if (t < 128) {
        float a = mb1[t];
#pragma unroll
        for (int d = 0; d < 16; d++) a = fmaf(p_s[d], mW1[d * 128 + t], a);
        mh_s[t] = fmaxf(a, 0.f);
    }
    __syncthreads();

    {
        float a = mb2[t];
#pragma unroll 8
        for (int u = 0; u < 128; u++) a = fmaf(mh_s[u], mW2[u * 256 + t], a);
        raw_s[t] = a;
    }
    __syncthreads();

    {
        int i = t >> 4, j = t & 15;
        float m = 0.5f * (raw_s[i * 16 + j] + raw_s[j * 16 + i]);
        if (i == j) m += EPS;
        met_s[t] = m;
        g_metric[b * 256 + t] = m;
    }
    __syncthreads();

    // points @ rW1[0:16] + rb1
    {
        float a = rb1[t];
#pragma unroll
        for (int d = 0; d < 16; d++) a = fmaf(p_s[d], rW1[d * 256 + t], a);
        g_pa[b * 256 + t] = a;
    }

    // Arow / Brow: metric row i through rW1 blocks [16:32] and [32:48]
    for (int i = 0; i < 16; i++) {
        float a = 0.f, c = 0.f;
#pragma unroll
        for (int d = 0; d < 16; d++) {
            float m = met_s[i * 16 + d];
            a = fmaf(m, rW1[(16 + d) * 256 + t], a);
            c = fmaf(m, rW1[(32 + d) * 256 + t], c);
        }
        g_ar[(b * 16 + i) * 256 + t] = a;
        g_br[(b * 16 + i) * 256 + t] = c;
    }
}

// ---------------------------------------------------------------------------
// Kernel 2: fused christoffel MLP + ricci layer-1 accumulate.
// grid = 4096 (b*16 + i), block = 256.
// Phase 1: thread = (j,k), computes christoffel[b,i,j,k] into smem.
// Phase 2: thread = hidden unit t, accumulates relu(layer1) over the 16 j's.
// ---------------------------------------------------------------------------
__global__ void chris_ricci_kernel(const float* __restrict__ cW1, const float* __restrict__ cb1,
                                   const float* __restrict__ cW2, const float* __restrict__ cb2,
                                   const float* __restrict__ rW1)
{
    int bi = blockIdx.x;
    int b = bi >> 4, i = bi & 15;
    int t = threadIdx.x;

    __shared__ float met_s[256];
    __shared__ float ch_s[256];
    __shared__ float w1_s[384];
    __shared__ float b1_s[128];
    __shared__ float w2_s[128];

    met_s[t] = g_metric[b * 256 + t];
    if (t < 128) { b1_s[t] = cb1[t]; w2_s[t] = cW2[t]; }
    else {
        int u = t - 128;
        w1_s[u] = cW1[u];
        w1_s[128 + u] = cW1[128 + u];
        w1_s[256 + u] = cW1[256 + u];
    }
    __syncthreads();

    // ---- christoffel: input (m[i][j], m[j][k], m[i][k]) -> tanh(128) -> 1
    {
        int j = t >> 4, k = t & 15;
        float x0 = met_s[i * 16 + j];
        float x1 = met_s[j * 16 + k];
        float x2 = met_s[i * 16 + k];
        float a0 = 0.f, a1 = 0.f, a2 = 0.f, a3 = 0.f;
#pragma unroll 4
        for (int u = 0; u < 128; u += 4) {
            float v0 = fmaf(w1_s[u + 0], x0, fmaf(w1_s[128 + u + 0], x1, fmaf(w1_s[256 + u + 0], x2, b1_s[u + 0])));
            float v1 = fmaf(w1_s[u + 1], x0, fmaf(w1_s[128 + u + 1], x1, fmaf(w1_s[256 + u + 1], x2, b1_s[u + 1])));
            float v2 = fmaf(w1_s[u + 2], x0, fmaf(w1_s[128 + u + 2], x1, fmaf(w1_s[256 + u + 2], x2, b1_s[u + 2])));
            float v3 = fmaf(w1_s[u + 3], x0, fmaf(w1_s[128 + u + 3], x1, fmaf(w1_s[256 + u + 3], x2, b1_s[u + 3])));
            a0 = fmaf(tanh_fast(v0), w2_s[u + 0], a0);
            a1 = fmaf(tanh_fast(v1), w2_s[u + 1], a1);
            a2 = fmaf(tanh_fast(v2), w2_s[u + 2], a2);
            a3 = fmaf(tanh_fast(v3), w2_s[u + 3], a3);
        }
        ch_s[t] = (a0 + a1) + (a2 + a3) + cb2[0];
    }
    __syncthreads();

    // ---- ricci layer-1: accumulate relu over j for hidden unit t
    float pa = g_pa[b * 256 + t] + g_ar[bi * 256 + t];
    float brw[16], w[16];
#pragma unroll
    for (int j = 0; j < 16; j++) brw[j] = g_br[(b * 16 + j) * 256 + t];
#pragma unroll
    for (int d = 0; d < 16; d++) w[d] = rW1[(48 + d) * 256 + t];

    float sacc = 0.f;
#pragma unroll
    for (int j = 0; j < 16; j++) {
        float v = pa + brw[j];
#pragma unroll
        for (int d = 0; d < 16; d++) v = fmaf(ch_s[j * 16 + d], w[d], v);
        sacc += fmaxf(v, 0.f);
    }
    g_spart[bi * 256 + t] = sacc;
}

// ---------------------------------------------------------------------------
// Kernel 3: reduce partials, collapsed GEMM2 (256-vec @ 256x256), symmetrize.
// grid = 256 (batch), block = 256.
// ---------------------------------------------------------------------------
__global__ void final_kernel(const float* __restrict__ rW2, const float* __restrict__ rb2,
                             float* __restrict__ out)
{
    int b = blockIdx.x;
    int t = threadIdx.x;
    __shared__ float s_s[256];
    __shared__ float S_s[256];

    float s = 0.f;
#pragma unroll
    for (int i = 0; i < 16; i++) s += g_spart[(b * 16 + i) * 256 + t];
    s_s[t] = s;
    __syncthreads();

    float a = 256.f * rb2[t];
#pragma unroll 8
    for (int u = 0; u < 256; u++) a = fmaf(s_s[u], rW2[u * 256 + t], a);
    S_s[t] = a;
    __syncthreads();

    int i = t >> 4, j = t & 15;
    out[b * 256 + t] = (S_s[t] + S_s[j * 16 + i]) * (0.5f / 256.f);
}

// ---------------------------------------------------------------------------
extern "C" void kernel_launch(void* const* d_in, const int* in_sizes, int n_in,
                              void* d_out, int out_size)
{
    const float* points = (const float*)d_in[0];
    const float* mW1 = (const float*)d_in[1];
    const float* mb1 = (const float*)d_in[2];
    const float* mW2 = (const float*)d_in[3];
    const float* mb2 = (const float*)d_in[4];
    const float* cW1 = (const float*)d_in[5];
    const float* cb1 = (const float*)d_in[6];
    const float* cW2 = (const float*)d_in[7];
    const float* cb2 = (const float*)d_in[8];
    const float* rW1 = (const float*)d_in[9];
    const float* rb1 = (const float*)d_in[10];
    const float* rW2 = (const float*)d_in[11];
    const float* rb2 = (const float*)d_in[12];
    float* out = (float*)d_out;

    prep_kernel<<<256, 256>>>(points, mW1, mb1, mW2, mb2, rW1, rb1);
    chris_ricci_kernel<<<4096, 256>>>(cW1, cb1, cW2, cb2, rW1);
    final_kernel<<<256, 256>>>(rW2, rb2, out);
}